// round 2
// baseline (speedup 1.0000x reference)
#include <cuda_runtime.h>

#define NN 100000
#define NE 1600000

// ---------------- device scratch (static globals: no runtime allocation) ----------------
__device__ float g_y[NN * 128];      // projected neighbor features (x @ Wn)
__device__ float g_s[NN * 128];      // self projection + bias (x @ Ws + b)
__device__ float g_x[NN * 128];      // activation buffer (in-place across layers)
__device__ float g_invdeg[NN];
__device__ int   g_rowptr[NN + 1];
__device__ int   g_cnt[NN];
__device__ int   g_tscan[NN];
__device__ int   g_bsum[128];
__device__ int   g_esrc[NE];         // src node ids grouped by dst (CSR payload)

// ---------------- CSR build ----------------
__global__ void k_zero_cnt() {
    int i = blockIdx.x * blockDim.x + threadIdx.x;
    if (i < NN) g_cnt[i] = 0;
}

__global__ void k_count(const int* __restrict__ dst) {
    int e = blockIdx.x * blockDim.x + threadIdx.x;
    if (e < NE) atomicAdd(&g_cnt[dst[e]], 1);
}

// per-1024-block inclusive scan of g_cnt -> g_tscan, block totals -> g_bsum
__global__ void k_scan1() {
    __shared__ int wsum[32];
    int i = blockIdx.x * 1024 + threadIdx.x;
    int lane = threadIdx.x & 31, wid = threadIdx.x >> 5;
    int v = (i < NN) ? g_cnt[i] : 0;
    int x = v;
#pragma unroll
    for (int o = 1; o < 32; o <<= 1) {
        int t = __shfl_up_sync(0xffffffffu, x, o);
        if (lane >= o) x += t;
    }
    if (lane == 31) wsum[wid] = x;
    __syncthreads();
    if (wid == 0) {
        int w = wsum[lane];
#pragma unroll
        for (int o = 1; o < 32; o <<= 1) {
            int t = __shfl_up_sync(0xffffffffu, w, o);
            if (lane >= o) w += t;
        }
        wsum[lane] = w;
    }
    __syncthreads();
    int off = wid ? wsum[wid - 1] : 0;
    int inc = x + off;
    if (i < NN) g_tscan[i] = inc;
    if (threadIdx.x == 1023) g_bsum[blockIdx.x] = inc;
}

// exclusive scan of the (<=128) block sums, single block of 128 threads
__global__ void k_scan2(int nb) {
    __shared__ int sm[128];
    int t = threadIdx.x;
    int v = (t < nb) ? g_bsum[t] : 0;
    sm[t] = v;
    __syncthreads();
    for (int o = 1; o < 128; o <<= 1) {
        int add = (t >= o) ? sm[t - o] : 0;
        __syncthreads();
        sm[t] += add;
        __syncthreads();
    }
    if (t < nb) g_bsum[t] = sm[t] - v;  // exclusive prefix
}

__global__ void k_scan3() {
    int i = blockIdx.x * blockDim.x + threadIdx.x;
    if (i < NN) {
        g_rowptr[i + 1] = g_tscan[i] + g_bsum[i >> 10];
        if (i == 0) g_rowptr[0] = 0;
        int d = g_cnt[i];
        g_invdeg[i] = 1.0f / (float)(d > 0 ? d : 1);
    }
}

__global__ void k_fill(const int* __restrict__ src, const int* __restrict__ dst) {
    int e = blockIdx.x * blockDim.x + threadIdx.x;
    if (e < NE) {
        int d = dst[e];
        int p = g_rowptr[d] + atomicAdd(&g_cnt[d], 1);
        g_esrc[p] = src[e];
    }
}

// ---------------- dual GEMM: y = x@Wn ; s = x@Ws + b  (K = 128 fixed) ----------------
// tile: 128 rows x (2C) cols, 256 threads, each thread 8 rows x (2C/16) cols
template <int C>
__global__ __launch_bounds__(256, 1) void k_gemm_dual(
    const float* __restrict__ x, const float* __restrict__ Wn,
    const float* __restrict__ Ws, const float* __restrict__ bias,
    float* __restrict__ y, float* __restrict__ s) {
    constexpr int C2 = 2 * C;
    constexpr int TC = C2 / 16;
    extern __shared__ float smarr[];
    float* Wsm = smarr;             // [128][C2]
    float* Xs = smarr + 128 * C2;   // [128][129] (padded rows)

    int tid = threadIdx.x;
    int row0 = blockIdx.x * 128;

    // stage concatenated weights [k][c]: c<C -> Wn, else Ws
    for (int idx = tid; idx < 128 * C2; idx += 256) {
        int k = idx / C2, c = idx - k * C2;
        Wsm[idx] = (c < C) ? Wn[k * C + c] : Ws[k * C + (c - C)];
    }
    // stage X tile (row-major, pad 129)
    for (int idx = tid; idx < 128 * 32; idx += 256) {
        int r = idx >> 5, k4 = (idx & 31) << 2;
        int grow = row0 + r;
        float4 v = make_float4(0.f, 0.f, 0.f, 0.f);
        if (grow < NN) v = *(const float4*)(x + grow * 128 + k4);
        float* p = &Xs[r * 129 + k4];
        p[0] = v.x; p[1] = v.y; p[2] = v.z; p[3] = v.w;
    }
    __syncthreads();

    int tx = tid & 15, ty = tid >> 4;
    float acc[8][TC];
#pragma unroll
    for (int i = 0; i < 8; i++)
#pragma unroll
        for (int j = 0; j < TC; j++) acc[i][j] = 0.f;

#pragma unroll 4
    for (int k = 0; k < 128; k++) {
        float a[8];
#pragma unroll
        for (int i = 0; i < 8; i++) a[i] = Xs[(ty * 8 + i) * 129 + k];
        float b[TC];
#pragma unroll
        for (int j = 0; j < TC; j++) b[j] = Wsm[k * C2 + tx + 16 * j];
#pragma unroll
        for (int i = 0; i < 8; i++)
#pragma unroll
            for (int j = 0; j < TC; j++) acc[i][j] = fmaf(a[i], b[j], acc[i][j]);
    }

#pragma unroll
    for (int i = 0; i < 8; i++) {
        int row = row0 + ty * 8 + i;
        if (row < NN) {
#pragma unroll
            for (int j = 0; j < TC; j++) {
                int c = tx + 16 * j;
                if (c < C) y[row * C + c] = acc[i][j];
                else       s[row * C + (c - C)] = acc[i][j] + bias[c - C];
            }
        }
    }
}

// ---------------- warp-per-node gather + finalize (F = 128) ----------------
template <bool RELU>
__global__ void k_aggfin128(const float4* __restrict__ y4, const float4* __restrict__ s4,
                            float4* __restrict__ out4) {
    int n = (blockIdx.x * blockDim.x + threadIdx.x) >> 5;
    int lane = threadIdx.x & 31;
    if (n >= NN) return;
    int r0 = g_rowptr[n], r1 = g_rowptr[n + 1];
    float4 acc = make_float4(0.f, 0.f, 0.f, 0.f);
    for (int base = r0; base < r1; base += 32) {
        int idx = base + lane;
        int sid = (idx < r1) ? g_esrc[idx] : 0;
        int m = r1 - base;
        if (m > 32) m = 32;
#pragma unroll 4
        for (int j = 0; j < m; j++) {
            int sn = __shfl_sync(0xffffffffu, sid, j);
            float4 v = y4[sn * 32 + lane];
            acc.x += v.x; acc.y += v.y; acc.z += v.z; acc.w += v.w;
        }
    }
    float id = g_invdeg[n];
    float4 sv = s4[n * 32 + lane];
    float4 o;
    o.x = sv.x + acc.x * id;
    o.y = sv.y + acc.y * id;
    o.z = sv.z + acc.z * id;
    o.w = sv.w + acc.w * id;
    if (RELU) {
        o.x = fmaxf(o.x, 0.f); o.y = fmaxf(o.y, 0.f);
        o.z = fmaxf(o.z, 0.f); o.w = fmaxf(o.w, 0.f);
    }
    out4[n * 32 + lane] = o;
}

// ---------------- warp-per-node gather + finalize (F = 40, no relu) ----------------
__global__ void k_aggfin40(const float* __restrict__ y, const float* __restrict__ s,
                           float* __restrict__ out) {
    int n = (blockIdx.x * blockDim.x + threadIdx.x) >> 5;
    int lane = threadIdx.x & 31;
    if (n >= NN) return;
    int r0 = g_rowptr[n], r1 = g_rowptr[n + 1];
    float acc0 = 0.f, acc1 = 0.f;
    for (int base = r0; base < r1; base += 32) {
        int idx = base + lane;
        int sid = (idx < r1) ? g_esrc[idx] : 0;
        int m = r1 - base;
        if (m > 32) m = 32;
#pragma unroll 4
        for (int j = 0; j < m; j++) {
            int sn = __shfl_sync(0xffffffffu, sid, j);
            const float* yr = y + sn * 40;
            acc0 += yr[lane];
            if (lane < 8) acc1 += yr[32 + lane];
        }
    }
    float id = g_invdeg[n];
    const float* sr = s + n * 40;
    out[n * 40 + lane] = sr[lane] + acc0 * id;
    if (lane < 8) out[n * 40 + 32 + lane] = sr[32 + lane] + acc1 * id;
}

// ---------------- launch ----------------
extern "C" void kernel_launch(void* const* d_in, const int* in_sizes, int n_in,
                              void* d_out, int out_size) {
    const float* feat = (const float*)d_in[0];
    const int* src = (const int*)d_in[1];
    const int* dst = (const int*)d_in[2];
    const float* Ws1 = (const float*)d_in[3];
    const float* Wn1 = (const float*)d_in[4];
    const float* b1  = (const float*)d_in[5];
    const float* Ws2 = (const float*)d_in[6];
    const float* Wn2 = (const float*)d_in[7];
    const float* b2  = (const float*)d_in[8];
    const float* Ws3 = (const float*)d_in[9];
    const float* Wn3 = (const float*)d_in[10];
    const float* b3  = (const float*)d_in[11];
    float* out = (float*)d_out;

    float *py, *ps, *px;
    cudaGetSymbolAddress((void**)&py, g_y);
    cudaGetSymbolAddress((void**)&ps, g_s);
    cudaGetSymbolAddress((void**)&px, g_x);

    const int SMEM128 = (128 * 256 + 128 * 129) * 4;  // 197120
    const int SMEM40  = (128 * 80 + 128 * 129) * 4;   // 107008
    cudaFuncSetAttribute(k_gemm_dual<128>, cudaFuncAttributeMaxDynamicSharedMemorySize, SMEM128);
    cudaFuncSetAttribute(k_gemm_dual<40>,  cudaFuncAttributeMaxDynamicSharedMemorySize, SMEM40);

    int nbN = (NN + 255) / 256;
    int nbE = (NE + 255) / 256;
    int nbScan = (NN + 1023) / 1024;  // 98
    int gGemm = (NN + 127) / 128;     // 782
    int gAgg = (NN + 7) / 8;          // 12500

    // CSR build (int atomics only)
    k_zero_cnt<<<nbN, 256>>>();
    k_count<<<nbE, 256>>>(dst);
    k_scan1<<<nbScan, 1024>>>();
    k_scan2<<<1, 128>>>(nbScan);
    k_scan3<<<nbN, 256>>>();
    k_zero_cnt<<<nbN, 256>>>();
    k_fill<<<nbE, 256>>>(src, dst);

    // layer 1
    k_gemm_dual<128><<<gGemm, 256, SMEM128>>>(feat, Wn1, Ws1, b1, py, ps);
    k_aggfin128<true><<<gAgg, 256>>>((const float4*)py, (const float4*)ps, (float4*)px);
    // layer 2
    k_gemm_dual<128><<<gGemm, 256, SMEM128>>>(px, Wn2, Ws2, b2, py, ps);
    k_aggfin128<true><<<gAgg, 256>>>((const float4*)py, (const float4*)ps, (float4*)px);
    // layer 3 (project to 40 first, then aggregate 40-dim)
    k_gemm_dual<40><<<gGemm, 256, SMEM40>>>(px, Wn3, Ws3, b3, py, ps);
    k_aggfin40<<<gAgg, 256>>>(py, ps, out);
}

// round 3
// speedup vs baseline: 1.1865x; 1.1865x over previous
#include <cuda_runtime.h>
#include <cuda_bf16.h>
#include <cstdint>

#define NN 100000
#define NE 1600000
#define KP 136   // padded K stride (bf16 elems): word stride 68 -> bank = 4r+tg, conflict-free

// ---------------- device scratch ----------------
__device__ float g_y[NN * 128];
__device__ float g_s[NN * 128];
__device__ float g_x[NN * 128];
__device__ float g_invdeg[NN];
__device__ int   g_rowptr[NN + 1];
__device__ int   g_cnt[NN];
__device__ int   g_tscan[NN];
__device__ int   g_bsum[128];
__device__ int   g_esrc[NE];

// ---------------- CSR build ----------------
__global__ void k_zero_cnt() {
    int i = blockIdx.x * blockDim.x + threadIdx.x;
    if (i < NN) g_cnt[i] = 0;
}

__global__ void k_count(const int* __restrict__ dst) {
    int e = blockIdx.x * blockDim.x + threadIdx.x;
    if (e < NE) atomicAdd(&g_cnt[dst[e]], 1);
}

__global__ void k_scan1() {
    __shared__ int wsum[32];
    int i = blockIdx.x * 1024 + threadIdx.x;
    int lane = threadIdx.x & 31, wid = threadIdx.x >> 5;
    int v = (i < NN) ? g_cnt[i] : 0;
    int x = v;
#pragma unroll
    for (int o = 1; o < 32; o <<= 1) {
        int t = __shfl_up_sync(0xffffffffu, x, o);
        if (lane >= o) x += t;
    }
    if (lane == 31) wsum[wid] = x;
    __syncthreads();
    if (wid == 0) {
        int w = wsum[lane];
#pragma unroll
        for (int o = 1; o < 32; o <<= 1) {
            int t = __shfl_up_sync(0xffffffffu, w, o);
            if (lane >= o) w += t;
        }
        wsum[lane] = w;
    }
    __syncthreads();
    int off = wid ? wsum[wid - 1] : 0;
    int inc = x + off;
    if (i < NN) g_tscan[i] = inc;
    if (threadIdx.x == 1023) g_bsum[blockIdx.x] = inc;
}

__global__ void k_scan2(int nb) {
    __shared__ int sm[128];
    int t = threadIdx.x;
    int v = (t < nb) ? g_bsum[t] : 0;
    sm[t] = v;
    __syncthreads();
    for (int o = 1; o < 128; o <<= 1) {
        int add = (t >= o) ? sm[t - o] : 0;
        __syncthreads();
        sm[t] += add;
        __syncthreads();
    }
    if (t < nb) g_bsum[t] = sm[t] - v;
}

__global__ void k_scan3() {
    int i = blockIdx.x * blockDim.x + threadIdx.x;
    if (i < NN) {
        g_rowptr[i + 1] = g_tscan[i] + g_bsum[i >> 10];
        if (i == 0) g_rowptr[0] = 0;
        int d = g_cnt[i];
        g_invdeg[i] = 1.0f / (float)(d > 0 ? d : 1);
        g_cnt[i] = 0;   // reset cursor for k_fill (saves a zero kernel)
    }
}

__global__ void k_fill(const int* __restrict__ src, const int* __restrict__ dst) {
    int e = blockIdx.x * blockDim.x + threadIdx.x;
    if (e < NE) {
        int d = dst[e];
        int p = g_rowptr[d] + atomicAdd(&g_cnt[d], 1);
        g_esrc[p] = src[e];
    }
}

// ---------------- split-bf16 tensor-core dual GEMM ----------------
// out cols 0..C-1 -> y = x@Wn ; cols C..2C-1 -> s = x@Ws + b
// CTA tile: 128 rows x NTILE cols, 256 threads (8 warps: 4 row x 2 col)
// precision: x = hi+lo (bf16), W = hi+lo; acc = Ah*Bh + Al*Bh + Ah*Bl (fp32 accum)

__device__ __forceinline__ void mma_bf16(float (&c)[4], const uint32_t (&a)[4],
                                         const uint32_t (&b)[2]) {
    asm volatile(
        "mma.sync.aligned.m16n8k16.row.col.f32.bf16.bf16.f32 "
        "{%0,%1,%2,%3}, {%4,%5,%6,%7}, {%8,%9}, {%0,%1,%2,%3};\n"
        : "+f"(c[0]), "+f"(c[1]), "+f"(c[2]), "+f"(c[3])
        : "r"(a[0]), "r"(a[1]), "r"(a[2]), "r"(a[3]), "r"(b[0]), "r"(b[1]));
}

template <int NTILE, int C>
__global__ __launch_bounds__(256, 1) void k_gemm_mma(
    const float* __restrict__ x, const float* __restrict__ Wn,
    const float* __restrict__ Ws, const float* __restrict__ bias,
    float* __restrict__ y, float* __restrict__ s) {
    extern __shared__ __nv_bfloat16 smarr[];
    __nv_bfloat16* Ah = smarr;                 // [128][KP]
    __nv_bfloat16* Al = Ah + 128 * KP;
    __nv_bfloat16* Bh = Al + 128 * KP;         // [NTILE][KP]  (n-major, k contiguous)
    __nv_bfloat16* Bl = Bh + NTILE * KP;

    int tid = threadIdx.x;
    int row0 = blockIdx.x * 128;
    int col0 = blockIdx.y * NTILE;

    // stage A (128x128 fp32 -> hi/lo bf16)
    for (int idx = tid; idx < 128 * 32; idx += 256) {
        int r = idx >> 5, k4 = (idx & 31) << 2;
        int grow = row0 + r;
        float4 v = make_float4(0.f, 0.f, 0.f, 0.f);
        if (grow < NN) v = *(const float4*)(x + grow * 128 + k4);
        float vv[4] = {v.x, v.y, v.z, v.w};
#pragma unroll
        for (int q = 0; q < 4; q++) {
            float f = vv[q];
            __nv_bfloat16 h = __float2bfloat16(f);
            __nv_bfloat16 l = __float2bfloat16(f - __bfloat162float(h));
            Ah[r * KP + k4 + q] = h;
            Al[r * KP + k4 + q] = l;
        }
    }
    // stage B transposed: Bs[n][k] = Wcat[k][col0+n]
    for (int idx = tid; idx < 128 * NTILE; idx += 256) {
        int k = idx / NTILE, j = idx - k * NTILE;
        int cc = col0 + j;
        float f = (cc < C) ? Wn[k * C + cc] : Ws[k * C + (cc - C)];
        __nv_bfloat16 h = __float2bfloat16(f);
        __nv_bfloat16 l = __float2bfloat16(f - __bfloat162float(h));
        Bh[j * KP + k] = h;
        Bl[j * KP + k] = l;
    }
    __syncthreads();

    constexpr int HN = NTILE / 2;   // cols per col-warp
    constexpr int NF = HN / 8;      // n-fragments per warp
    int wid = tid >> 5, lane = tid & 31;
    int warpRow = wid >> 1;         // 0..3 -> 32 rows each
    int warpCol = wid & 1;          // 0..1
    int r = lane >> 2, tg = lane & 3;
    int mbase = warpRow * 32;
    int nbase = warpCol * HN;

    float acc[2][NF][4];
#pragma unroll
    for (int mi = 0; mi < 2; mi++)
#pragma unroll
        for (int ni = 0; ni < NF; ni++)
#pragma unroll
            for (int q = 0; q < 4; q++) acc[mi][ni][q] = 0.f;

#pragma unroll
    for (int kc = 0; kc < 8; kc++) {
        int k0 = kc * 16;
        uint32_t ah[2][4], al[2][4];
#pragma unroll
        for (int mi = 0; mi < 2; mi++) {
            int rr = mbase + mi * 16;
            const __nv_bfloat16* p0 = &Ah[(rr + r) * KP + k0 + tg * 2];
            const __nv_bfloat16* p1 = &Ah[(rr + r + 8) * KP + k0 + tg * 2];
            ah[mi][0] = *(const uint32_t*)p0;
            ah[mi][1] = *(const uint32_t*)p1;
            ah[mi][2] = *(const uint32_t*)(p0 + 8);
            ah[mi][3] = *(const uint32_t*)(p1 + 8);
            const __nv_bfloat16* q0 = &Al[(rr + r) * KP + k0 + tg * 2];
            const __nv_bfloat16* q1 = &Al[(rr + r + 8) * KP + k0 + tg * 2];
            al[mi][0] = *(const uint32_t*)q0;
            al[mi][1] = *(const uint32_t*)q1;
            al[mi][2] = *(const uint32_t*)(q0 + 8);
            al[mi][3] = *(const uint32_t*)(q1 + 8);
        }
        uint32_t bh[NF][2], bl[NF][2];
#pragma unroll
        for (int ni = 0; ni < NF; ni++) {
            const __nv_bfloat16* p = &Bh[(nbase + ni * 8 + r) * KP + k0 + tg * 2];
            bh[ni][0] = *(const uint32_t*)p;
            bh[ni][1] = *(const uint32_t*)(p + 8);
            const __nv_bfloat16* q = &Bl[(nbase + ni * 8 + r) * KP + k0 + tg * 2];
            bl[ni][0] = *(const uint32_t*)q;
            bl[ni][1] = *(const uint32_t*)(q + 8);
        }
#pragma unroll
        for (int mi = 0; mi < 2; mi++)
#pragma unroll
            for (int ni = 0; ni < NF; ni++) {
                mma_bf16(acc[mi][ni], ah[mi], bh[ni]);
                mma_bf16(acc[mi][ni], al[mi], bh[ni]);
                mma_bf16(acc[mi][ni], ah[mi], bl[ni]);
            }
    }

    // epilogue
#pragma unroll
    for (int mi = 0; mi < 2; mi++) {
#pragma unroll
        for (int ni = 0; ni < NF; ni++) {
            int grow0 = row0 + mbase + mi * 16 + r;
            int grow1 = grow0 + 8;
            int cc = col0 + nbase + ni * 8 + tg * 2;  // concat col (0..2C-1)
#pragma unroll
            for (int half = 0; half < 2; half++) {
                int grow = half ? grow1 : grow0;
                if (grow >= NN) continue;
                float v0 = acc[mi][ni][half * 2 + 0];
                float v1 = acc[mi][ni][half * 2 + 1];
                if (cc < C) {
                    *(float2*)(y + grow * C + cc) = make_float2(v0, v1);
                } else {
                    int c = cc - C;
                    *(float2*)(s + grow * C + c) =
                        make_float2(v0 + bias[c], v1 + bias[c + 1]);
                }
            }
        }
    }
}

// ---------------- warp-per-node gather + finalize (F = 128) ----------------
template <bool RELU>
__global__ void k_aggfin128(const float4* __restrict__ y4, const float4* __restrict__ s4,
                            float4* __restrict__ out4) {
    int n = (blockIdx.x * blockDim.x + threadIdx.x) >> 5;
    int lane = threadIdx.x & 31;
    if (n >= NN) return;
    int r0 = g_rowptr[n], r1 = g_rowptr[n + 1];
    float4 acc = make_float4(0.f, 0.f, 0.f, 0.f);
    for (int base = r0; base < r1; base += 32) {
        int idx = base + lane;
        int sid = (idx < r1) ? g_esrc[idx] : 0;
        int m = r1 - base;
        if (m > 32) m = 32;
#pragma unroll 4
        for (int j = 0; j < m; j++) {
            int sn = __shfl_sync(0xffffffffu, sid, j);
            float4 v = y4[sn * 32 + lane];
            acc.x += v.x; acc.y += v.y; acc.z += v.z; acc.w += v.w;
        }
    }
    float id = g_invdeg[n];
    float4 sv = s4[n * 32 + lane];
    float4 o;
    o.x = sv.x + acc.x * id;
    o.y = sv.y + acc.y * id;
    o.z = sv.z + acc.z * id;
    o.w = sv.w + acc.w * id;
    if (RELU) {
        o.x = fmaxf(o.x, 0.f); o.y = fmaxf(o.y, 0.f);
        o.z = fmaxf(o.z, 0.f); o.w = fmaxf(o.w, 0.f);
    }
    out4[n * 32 + lane] = o;
}

// ---------------- warp-per-node gather + finalize (F = 40) ----------------
__global__ void k_aggfin40(const float* __restrict__ y, const float* __restrict__ s,
                           float* __restrict__ out) {
    int n = (blockIdx.x * blockDim.x + threadIdx.x) >> 5;
    int lane = threadIdx.x & 31;
    if (n >= NN) return;
    int r0 = g_rowptr[n], r1 = g_rowptr[n + 1];
    float acc0 = 0.f, acc1 = 0.f;
    for (int base = r0; base < r1; base += 32) {
        int idx = base + lane;
        int sid = (idx < r1) ? g_esrc[idx] : 0;
        int m = r1 - base;
        if (m > 32) m = 32;
#pragma unroll 4
        for (int j = 0; j < m; j++) {
            int sn = __shfl_sync(0xffffffffu, sid, j);
            const float* yr = y + sn * 40;
            acc0 += yr[lane];
            if (lane < 8) acc1 += yr[32 + lane];
        }
    }
    float id = g_invdeg[n];
    const float* sr = s + n * 40;
    out[n * 40 + lane] = sr[lane] + acc0 * id;
    if (lane < 8) out[n * 40 + 32 + lane] = sr[32 + lane] + acc1 * id;
}

// ---------------- launch ----------------
extern "C" void kernel_launch(void* const* d_in, const int* in_sizes, int n_in,
                              void* d_out, int out_size) {
    const float* feat = (const float*)d_in[0];
    const int* src = (const int*)d_in[1];
    const int* dst = (const int*)d_in[2];
    const float* Ws1 = (const float*)d_in[3];
    const float* Wn1 = (const float*)d_in[4];
    const float* b1  = (const float*)d_in[5];
    const float* Ws2 = (const float*)d_in[6];
    const float* Wn2 = (const float*)d_in[7];
    const float* b2  = (const float*)d_in[8];
    const float* Ws3 = (const float*)d_in[9];
    const float* Wn3 = (const float*)d_in[10];
    const float* b3  = (const float*)d_in[11];
    float* out = (float*)d_out;

    float *py, *ps, *px;
    cudaGetSymbolAddress((void**)&py, g_y);
    cudaGetSymbolAddress((void**)&ps, g_s);
    cudaGetSymbolAddress((void**)&px, g_x);

    const int SMEM128 = (128 + 128 + 128 + 128) * KP * 2;  // 139264
    const int SMEM80  = (128 + 128 + 80 + 80) * KP * 2;    // 113152
    cudaFuncSetAttribute(k_gemm_mma<128, 128>, cudaFuncAttributeMaxDynamicSharedMemorySize, SMEM128);
    cudaFuncSetAttribute(k_gemm_mma<80, 40>,   cudaFuncAttributeMaxDynamicSharedMemorySize, SMEM80);

    int nbN = (NN + 255) / 256;
    int nbE = (NE + 255) / 256;
    int nbScan = (NN + 1023) / 1024;  // 98
    int gRows = (NN + 127) / 128;     // 782
    int gAgg = (NN + 7) / 8;          // 12500

    // CSR build
    k_zero_cnt<<<nbN, 256>>>();
    k_count<<<nbE, 256>>>(dst);
    k_scan1<<<nbScan, 1024>>>();
    k_scan2<<<1, 128>>>(nbScan);
    k_scan3<<<nbN, 256>>>();
    k_fill<<<nbE, 256>>>(src, dst);

    // layer 1
    k_gemm_mma<128, 128><<<dim3(gRows, 2), 256, SMEM128>>>(feat, Wn1, Ws1, b1, py, ps);
    k_aggfin128<true><<<gAgg, 256>>>((const float4*)py, (const float4*)ps, (float4*)px);
    // layer 2
    k_gemm_mma<128, 128><<<dim3(gRows, 2), 256, SMEM128>>>(px, Wn2, Ws2, b2, py, ps);
    k_aggfin128<true><<<gAgg, 256>>>((const float4*)py, (const float4*)ps, (float4*)px);
    // layer 3 (project to 40 cols x2, then aggregate 40-dim)
    k_gemm_mma<80, 40><<<dim3(gRows, 1), 256, SMEM80>>>(px, Wn3, Ws3, b3, py, ps);
    k_aggfin40<<<gAgg, 256>>>(py, ps, out);
}

// round 5
// speedup vs baseline: 1.5889x; 1.3392x over previous
#include <cuda_runtime.h>
#include <cuda_bf16.h>
#include <cstdint>

#define NN 100000
#define NE 1600000
#define KP 136   // padded K stride (bf16): row stride 68 words -> ldmatrix conflict-free

// ---------------- device scratch ----------------
__device__ float g_y[NN * 128];
__device__ float g_s[NN * 128];
__device__ __nv_bfloat16 g_xh[NN * 128];
__device__ __nv_bfloat16 g_xl[NN * 128];
__device__ __nv_bfloat16 g_w1h[256 * 128], g_w1l[256 * 128];
__device__ __nv_bfloat16 g_w2h[256 * 128], g_w2l[256 * 128];
__device__ __nv_bfloat16 g_w3h[128 * 128], g_w3l[128 * 128];
__device__ float g_invdeg[NN];
__device__ int   g_rowptr[NN + 1];
__device__ int   g_cnt[NN];
__device__ int   g_tscan[NN];
__device__ int   g_bsum[128];
__device__ int   g_esrc[NE];

__device__ __forceinline__ uint32_t smem_u32(const void* p) {
    uint32_t a;
    asm("{ .reg .u64 t; cvta.to.shared.u64 t, %1; cvt.u32.u64 %0, t; }" : "=r"(a) : "l"(p));
    return a;
}

// ---------------- CSR build ----------------
__global__ void k_zero_cnt() {
    int i = blockIdx.x * blockDim.x + threadIdx.x;
    if (i < NN) g_cnt[i] = 0;
}
__global__ void k_count(const int* __restrict__ dst) {
    int e = blockIdx.x * blockDim.x + threadIdx.x;
    if (e < NE) atomicAdd(&g_cnt[dst[e]], 1);
}
__global__ void k_scan1() {
    __shared__ int wsum[32];
    int i = blockIdx.x * 1024 + threadIdx.x;
    int lane = threadIdx.x & 31, wid = threadIdx.x >> 5;
    int v = (i < NN) ? g_cnt[i] : 0;
    int x = v;
#pragma unroll
    for (int o = 1; o < 32; o <<= 1) {
        int t = __shfl_up_sync(0xffffffffu, x, o);
        if (lane >= o) x += t;
    }
    if (lane == 31) wsum[wid] = x;
    __syncthreads();
    if (wid == 0) {
        int w = wsum[lane];
#pragma unroll
        for (int o = 1; o < 32; o <<= 1) {
            int t = __shfl_up_sync(0xffffffffu, w, o);
            if (lane >= o) w += t;
        }
        wsum[lane] = w;
    }
    __syncthreads();
    int off = wid ? wsum[wid - 1] : 0;
    int inc = x + off;
    if (i < NN) g_tscan[i] = inc;
    if (threadIdx.x == 1023) g_bsum[blockIdx.x] = inc;
}
__global__ void k_scan2(int nb) {
    __shared__ int sm[128];
    int t = threadIdx.x;
    int v = (t < nb) ? g_bsum[t] : 0;
    sm[t] = v;
    __syncthreads();
    for (int o = 1; o < 128; o <<= 1) {
        int add = (t >= o) ? sm[t - o] : 0;
        __syncthreads();
        sm[t] += add;
        __syncthreads();
    }
    if (t < nb) g_bsum[t] = sm[t] - v;
}
__global__ void k_scan3() {
    int i = blockIdx.x * blockDim.x + threadIdx.x;
    if (i < NN) {
        g_rowptr[i + 1] = g_tscan[i] + g_bsum[i >> 10];
        if (i == 0) g_rowptr[0] = 0;
        int d = g_cnt[i];
        g_invdeg[i] = 1.0f / (float)(d > 0 ? d : 1);
        g_cnt[i] = 0;
    }
}
__global__ void k_fill(const int* __restrict__ src, const int* __restrict__ dst) {
    int e = blockIdx.x * blockDim.x + threadIdx.x;
    if (e < NE) {
        int d = dst[e];
        int p = g_rowptr[d] + atomicAdd(&g_cnt[d], 1);
        g_esrc[p] = src[e];
    }
}

// ---------------- prep: weights -> [n][k] K-major bf16 hi/lo (zero-padded) ----------------
__global__ void k_prepW(const float* __restrict__ Wn, const float* __restrict__ Ws,
                        int C, int NT, __nv_bfloat16* __restrict__ oh,
                        __nv_bfloat16* __restrict__ ol) {
    int idx = blockIdx.x * blockDim.x + threadIdx.x;
    if (idx >= NT * 128) return;
    int n = idx >> 7, k = idx & 127;
    float f = 0.f;
    if (n < C) f = Wn[k * C + n];
    else if (n < 2 * C) f = Ws[k * C + (n - C)];
    __nv_bfloat16 h = __float2bfloat16(f);
    oh[idx] = h;
    ol[idx] = __float2bfloat16(f - __bfloat162float(h));
}

// features -> bf16 hi/lo
__global__ void k_splitX(const float4* __restrict__ x4, uint2* __restrict__ xh2,
                         uint2* __restrict__ xl2) {
    int idx = blockIdx.x * blockDim.x + threadIdx.x;
    if (idx >= NN * 32) return;
    float4 v = x4[idx];
    __nv_bfloat16 hx = __float2bfloat16(v.x), hy = __float2bfloat16(v.y);
    __nv_bfloat16 hz = __float2bfloat16(v.z), hw = __float2bfloat16(v.w);
    __nv_bfloat162 h01(hx, hy), h23(hz, hw);
    __nv_bfloat162 l01(__float2bfloat16(v.x - __bfloat162float(hx)),
                       __float2bfloat16(v.y - __bfloat162float(hy)));
    __nv_bfloat162 l23(__float2bfloat16(v.z - __bfloat162float(hz)),
                       __float2bfloat16(v.w - __bfloat162float(hw)));
    xh2[idx] = make_uint2(*(uint32_t*)&h01, *(uint32_t*)&h23);
    xl2[idx] = make_uint2(*(uint32_t*)&l01, *(uint32_t*)&l23);
}

// ---------------- mma.sync bf16 dual GEMM, occ-2, ldmatrix fragments ----------------
__device__ __forceinline__ void mma_bf16(float (&c)[4], const uint32_t (&a)[4],
                                         const uint32_t b0, const uint32_t b1) {
    asm volatile(
        "mma.sync.aligned.m16n8k16.row.col.f32.bf16.bf16.f32 "
        "{%0,%1,%2,%3}, {%4,%5,%6,%7}, {%8,%9}, {%0,%1,%2,%3};\n"
        : "+f"(c[0]), "+f"(c[1]), "+f"(c[2]), "+f"(c[3])
        : "r"(a[0]), "r"(a[1]), "r"(a[2]), "r"(a[3]), "r"(b0), "r"(b1));
}
__device__ __forceinline__ void ldsm_x4(uint32_t (&r)[4], uint32_t addr) {
    asm volatile("ldmatrix.sync.aligned.m8n8.x4.shared.b16 {%0,%1,%2,%3}, [%4];"
                 : "=r"(r[0]), "=r"(r[1]), "=r"(r[2]), "=r"(r[3]) : "r"(addr));
}

// CTA tile: 128 rows x 64 cols of the concatenated output [y | s] (width 2C padded).
// 8 warps: 4 row-groups x 2 col-groups. Each warp: 32 rows x 32 cols.
__global__ __launch_bounds__(256, 2) void k_gemm_mma(
    const __nv_bfloat16* __restrict__ xh, const __nv_bfloat16* __restrict__ xl,
    const __nv_bfloat16* __restrict__ wh, const __nv_bfloat16* __restrict__ wl,
    const float* __restrict__ bias, int C,
    float* __restrict__ y, float* __restrict__ s) {
    extern __shared__ __nv_bfloat16 smarr[];
    __nv_bfloat16* Ah = smarr;                // [128][KP]
    __nv_bfloat16* Al = Ah + 128 * KP;
    __nv_bfloat16* Bh = Al + 128 * KP;        // [64][KP]
    __nv_bfloat16* Bl = Bh + 64 * KP;

    int tid = threadIdx.x;
    int row0 = blockIdx.x * 128;
    int col0 = blockIdx.y * 64;

    // stage A (pure bf16 copy)
    for (int idx = tid; idx < 128 * 16; idx += 256) {
        int r = idx >> 4, k = (idx & 15) << 3;
        int grow = row0 + r;
        uint4 vh = make_uint4(0, 0, 0, 0), vl = vh;
        if (grow < NN) {
            vh = *(const uint4*)(xh + grow * 128 + k);
            vl = *(const uint4*)(xl + grow * 128 + k);
        }
        *(uint4*)(Ah + r * KP + k) = vh;
        *(uint4*)(Al + r * KP + k) = vl;
    }
    // stage B
    for (int idx = tid; idx < 64 * 16; idx += 256) {
        int n = idx >> 4, k = (idx & 15) << 3;
        *(uint4*)(Bh + n * KP + k) = *(const uint4*)(wh + (col0 + n) * 128 + k);
        *(uint4*)(Bl + n * KP + k) = *(const uint4*)(wl + (col0 + n) * 128 + k);
    }
    __syncthreads();

    int wid = tid >> 5, lane = tid & 31;
    int mbase = (wid >> 1) * 32;
    int nbase = (wid & 1) * 32;
    int r4 = lane >> 2, tg = lane & 3;

    uint32_t aBase = smem_u32(Ah);
    uint32_t alBase = smem_u32(Al);
    uint32_t bBase = smem_u32(Bh);
    uint32_t blBase = smem_u32(Bl);

    // ldmatrix lane address offsets (element units)
    int aRow = mbase + (lane & 15);
    int aOff = aRow * KP + ((lane >> 4) << 3);          // +k0, +mi*16*KP
    int q = lane >> 3;
    int bRow = nbase + ((q >> 1) << 3) + (lane & 7);
    int bOff = bRow * KP + ((q & 1) << 3);              // +k0, +16*KP for nf pair 2,3

    float acc[2][4][4];
#pragma unroll
    for (int mi = 0; mi < 2; mi++)
#pragma unroll
        for (int ni = 0; ni < 4; ni++)
#pragma unroll
            for (int c = 0; c < 4; c++) acc[mi][ni][c] = 0.f;

#pragma unroll
    for (int kc = 0; kc < 8; kc++) {
        int k0 = kc * 16;
        uint32_t ah[2][4], al[2][4];
        ldsm_x4(ah[0], aBase + (aOff + k0) * 2);
        ldsm_x4(ah[1], aBase + (aOff + 16 * KP + k0) * 2);
        ldsm_x4(al[0], alBase + (aOff + k0) * 2);
        ldsm_x4(al[1], alBase + (aOff + 16 * KP + k0) * 2);
        uint32_t bh01[4], bh23[4], bl01[4], bl23[4];
        ldsm_x4(bh01, bBase + (bOff + k0) * 2);
        ldsm_x4(bh23, bBase + (bOff + 16 * KP + k0) * 2);
        ldsm_x4(bl01, blBase + (bOff + k0) * 2);
        ldsm_x4(bl23, blBase + (bOff + 16 * KP + k0) * 2);
#pragma unroll
        for (int mi = 0; mi < 2; mi++) {
            mma_bf16(acc[mi][0], ah[mi], bh01[0], bh01[1]);
            mma_bf16(acc[mi][1], ah[mi], bh01[2], bh01[3]);
            mma_bf16(acc[mi][2], ah[mi], bh23[0], bh23[1]);
            mma_bf16(acc[mi][3], ah[mi], bh23[2], bh23[3]);
            mma_bf16(acc[mi][0], al[mi], bh01[0], bh01[1]);
            mma_bf16(acc[mi][1], al[mi], bh01[2], bh01[3]);
            mma_bf16(acc[mi][2], al[mi], bh23[0], bh23[1]);
            mma_bf16(acc[mi][3], al[mi], bh23[2], bh23[3]);
            mma_bf16(acc[mi][0], ah[mi], bl01[0], bl01[1]);
            mma_bf16(acc[mi][1], ah[mi], bl01[2], bl01[3]);
            mma_bf16(acc[mi][2], ah[mi], bl23[0], bl23[1]);
            mma_bf16(acc[mi][3], ah[mi], bl23[2], bl23[3]);
        }
    }

    // epilogue
#pragma unroll
    for (int mi = 0; mi < 2; mi++) {
#pragma unroll
        for (int ni = 0; ni < 4; ni++) {
            int grow0 = row0 + mbase + mi * 16 + r4;
            int cc = col0 + nbase + ni * 8 + tg * 2;
            if (cc >= 2 * C) continue;
#pragma unroll
            for (int half = 0; half < 2; half++) {
                int grow = grow0 + half * 8;
                if (grow >= NN) continue;
                float v0 = acc[mi][ni][half * 2 + 0];
                float v1 = acc[mi][ni][half * 2 + 1];
                if (cc < C) {
                    *(float2*)(y + grow * C + cc) = make_float2(v0, v1);
                } else {
                    int c = cc - C;
                    *(float2*)(s + grow * C + c) =
                        make_float2(v0 + bias[c], v1 + bias[c + 1]);
                }
            }
        }
    }
}

// ---------------- warp-per-node gather + finalize (F=128) -> bf16 hi/lo ----------------
__global__ void k_aggfin128sp(const float4* __restrict__ y4, const float4* __restrict__ s4,
                              uint2* __restrict__ xh2, uint2* __restrict__ xl2) {
    int n = (blockIdx.x * blockDim.x + threadIdx.x) >> 5;
    int lane = threadIdx.x & 31;
    if (n >= NN) return;
    int r0 = g_rowptr[n], r1 = g_rowptr[n + 1];
    float4 acc = make_float4(0.f, 0.f, 0.f, 0.f);
    for (int base = r0; base < r1; base += 32) {
        int idx = base + lane;
        int sid = (idx < r1) ? g_esrc[idx] : 0;
        int m = r1 - base;
        if (m > 32) m = 32;
#pragma unroll 4
        for (int j = 0; j < m; j++) {
            int sn = __shfl_sync(0xffffffffu, sid, j);
            float4 v = y4[sn * 32 + lane];
            acc.x += v.x; acc.y += v.y; acc.z += v.z; acc.w += v.w;
        }
    }
    float id = g_invdeg[n];
    float4 sv = s4[n * 32 + lane];
    float4 o;
    o.x = fmaxf(sv.x + acc.x * id, 0.f);
    o.y = fmaxf(sv.y + acc.y * id, 0.f);
    o.z = fmaxf(sv.z + acc.z * id, 0.f);
    o.w = fmaxf(sv.w + acc.w * id, 0.f);
    __nv_bfloat16 hx = __float2bfloat16(o.x), hy = __float2bfloat16(o.y);
    __nv_bfloat16 hz = __float2bfloat16(o.z), hw = __float2bfloat16(o.w);
    __nv_bfloat162 h01(hx, hy), h23(hz, hw);
    __nv_bfloat162 l01(__float2bfloat16(o.x - __bfloat162float(hx)),
                       __float2bfloat16(o.y - __bfloat162float(hy)));
    __nv_bfloat162 l23(__float2bfloat16(o.z - __bfloat162float(hz)),
                       __float2bfloat16(o.w - __bfloat162float(hw)));
    xh2[n * 32 + lane] = make_uint2(*(uint32_t*)&h01, *(uint32_t*)&h23);
    xl2[n * 32 + lane] = make_uint2(*(uint32_t*)&l01, *(uint32_t*)&l23);
}

// ---------------- warp-per-node gather + finalize (F=40) ----------------
__global__ void k_aggfin40(const float* __restrict__ y, const float* __restrict__ s,
                           float* __restrict__ out) {
    int n = (blockIdx.x * blockDim.x + threadIdx.x) >> 5;
    int lane = threadIdx.x & 31;
    if (n >= NN) return;
    int r0 = g_rowptr[n], r1 = g_rowptr[n + 1];
    float acc0 = 0.f, acc1 = 0.f;
    for (int base = r0; base < r1; base += 32) {
        int idx = base + lane;
        int sid = (idx < r1) ? g_esrc[idx] : 0;
        int m = r1 - base;
        if (m > 32) m = 32;
#pragma unroll 4
        for (int j = 0; j < m; j++) {
            int sn = __shfl_sync(0xffffffffu, sid, j);
            const float* yr = y + sn * 40;
            acc0 += yr[lane];
            if (lane < 8) acc1 += yr[32 + lane];
        }
    }
    float id = g_invdeg[n];
    const float* sr = s + n * 40;
    out[n * 40 + lane] = sr[lane] + acc0 * id;
    if (lane < 8) out[n * 40 + 32 + lane] = sr[32 + lane] + acc1 * id;
}

// ---------------- launch ----------------
extern "C" void kernel_launch(void* const* d_in, const int* in_sizes, int n_in,
                              void* d_out, int out_size) {
    const float* feat = (const float*)d_in[0];
    const int* src = (const int*)d_in[1];
    const int* dst = (const int*)d_in[2];
    const float* Ws1 = (const float*)d_in[3];
    const float* Wn1 = (const float*)d_in[4];
    const float* b1  = (const float*)d_in[5];
    const float* Ws2 = (const float*)d_in[6];
    const float* Wn2 = (const float*)d_in[7];
    const float* b2  = (const float*)d_in[8];
    const float* Ws3 = (const float*)d_in[9];
    const float* Wn3 = (const float*)d_in[10];
    const float* b3  = (const float*)d_in[11];
    float* out = (float*)d_out;

    float *py, *ps;
    __nv_bfloat16 *pxh, *pxl, *pw1h, *pw1l, *pw2h, *pw2l, *pw3h, *pw3l;
    cudaGetSymbolAddress((void**)&py, g_y);
    cudaGetSymbolAddress((void**)&ps, g_s);
    cudaGetSymbolAddress((void**)&pxh, g_xh);
    cudaGetSymbolAddress((void**)&pxl, g_xl);
    cudaGetSymbolAddress((void**)&pw1h, g_w1h);
    cudaGetSymbolAddress((void**)&pw1l, g_w1l);
    cudaGetSymbolAddress((void**)&pw2h, g_w2h);
    cudaGetSymbolAddress((void**)&pw2l, g_w2l);
    cudaGetSymbolAddress((void**)&pw3h, g_w3h);
    cudaGetSymbolAddress((void**)&pw3l, g_w3l);

    const int SMEM = (128 + 128 + 64 + 64) * KP * 2;  // 104448
    cudaFuncSetAttribute(k_gemm_mma, cudaFuncAttributeMaxDynamicSharedMemorySize, SMEM);

    int nbN = (NN + 255) / 256;
    int nbE = (NE + 255) / 256;
    int nbScan = (NN + 1023) / 1024;
    int gRows = (NN + 127) / 128;   // 782
    int gAgg = (NN + 7) / 8;

    // prep (independent of CSR)
    k_prepW<<<(256 * 128 + 255) / 256, 256>>>(Wn1, Ws1, 128, 256, pw1h, pw1l);
    k_prepW<<<(256 * 128 + 255) / 256, 256>>>(Wn2, Ws2, 128, 256, pw2h, pw2l);
    k_prepW<<<(128 * 128 + 255) / 256, 256>>>(Wn3, Ws3, 40, 128, pw3h, pw3l);
    k_splitX<<<(NN * 32 + 255) / 256, 256>>>((const float4*)feat, (uint2*)pxh, (uint2*)pxl);

    // CSR build
    k_zero_cnt<<<nbN, 256>>>();
    k_count<<<nbE, 256>>>(dst);
    k_scan1<<<nbScan, 1024>>>();
    k_scan2<<<1, 128>>>(nbScan);
    k_scan3<<<nbN, 256>>>();
    k_fill<<<nbE, 256>>>(src, dst);

    // layer 1
    k_gemm_mma<<<dim3(gRows, 4), 256, SMEM>>>(pxh, pxl, pw1h, pw1l, b1, 128, py, ps);
    k_aggfin128sp<<<gAgg, 256>>>((const float4*)py, (const float4*)ps, (uint2*)pxh, (uint2*)pxl);
    // layer 2
    k_gemm_mma<<<dim3(gRows, 4), 256, SMEM>>>(pxh, pxl, pw2h, pw2l, b2, 128, py, ps);
    k_aggfin128sp<<<gAgg, 256>>>((const float4*)py, (const float4*)ps, (uint2*)pxh, (uint2*)pxl);
    // layer 3 (N padded to 128: cols 0..39 -> y, 40..79 -> s, rest dropped)
    k_gemm_mma<<<dim3(gRows, 2), 256, SMEM>>>(pxh, pxl, pw3h, pw3l, b3, 40, py, ps);
    k_aggfin40<<<gAgg, 256>>>(py, ps, out);
}

// round 6
// speedup vs baseline: 1.7035x; 1.0721x over previous
#include <cuda_runtime.h>
#include <cuda_bf16.h>
#include <cuda_fp16.h>
#include <cstdint>

#define NN 100000
#define NE 1600000
#define KP 136   // padded K stride (bf16): row stride 68 words -> ldmatrix conflict-free

// ---------------- device scratch ----------------
__device__ __half g_y[NN * 128];     // neighbor projection, fp16 (gather traffic /2)
__device__ float g_s[NN * 128];      // self projection + bias, fp32
__device__ __nv_bfloat16 g_xh[NN * 128];
__device__ __nv_bfloat16 g_xl[NN * 128];
__device__ __nv_bfloat16 g_w1h[256 * 128], g_w1l[256 * 128];
__device__ __nv_bfloat16 g_w2h[256 * 128], g_w2l[256 * 128];
__device__ __nv_bfloat16 g_w3h[128 * 128], g_w3l[128 * 128];
__device__ float g_invdeg[NN];
__device__ int   g_rowptr[NN + 1];
__device__ int   g_cnt[NN];
__device__ int   g_tscan[NN];
__device__ int   g_bsum[128];
__device__ int   g_esrc[NE];

__device__ __forceinline__ uint32_t smem_u32(const void* p) {
    uint32_t a;
    asm("{ .reg .u64 t; cvta.to.shared.u64 t, %1; cvt.u32.u64 %0, t; }" : "=r"(a) : "l"(p));
    return a;
}

// ---------------- CSR build ----------------
__global__ void k_zero_cnt() {
    int i = blockIdx.x * blockDim.x + threadIdx.x;
    if (i < NN) g_cnt[i] = 0;
}
__global__ void k_count(const int* __restrict__ dst) {
    int e = blockIdx.x * blockDim.x + threadIdx.x;
    if (e < NE) atomicAdd(&g_cnt[dst[e]], 1);
}
__global__ void k_scan1() {
    __shared__ int wsum[32];
    int i = blockIdx.x * 1024 + threadIdx.x;
    int lane = threadIdx.x & 31, wid = threadIdx.x >> 5;
    int v = (i < NN) ? g_cnt[i] : 0;
    int x = v;
#pragma unroll
    for (int o = 1; o < 32; o <<= 1) {
        int t = __shfl_up_sync(0xffffffffu, x, o);
        if (lane >= o) x += t;
    }
    if (lane == 31) wsum[wid] = x;
    __syncthreads();
    if (wid == 0) {
        int w = wsum[lane];
#pragma unroll
        for (int o = 1; o < 32; o <<= 1) {
            int t = __shfl_up_sync(0xffffffffu, w, o);
            if (lane >= o) w += t;
        }
        wsum[lane] = w;
    }
    __syncthreads();
    int off = wid ? wsum[wid - 1] : 0;
    int inc = x + off;
    if (i < NN) g_tscan[i] = inc;
    if (threadIdx.x == 1023) g_bsum[blockIdx.x] = inc;
}
__global__ void k_scan2(int nb) {
    __shared__ int sm[128];
    int t = threadIdx.x;
    int v = (t < nb) ? g_bsum[t] : 0;
    sm[t] = v;
    __syncthreads();
    for (int o = 1; o < 128; o <<= 1) {
        int add = (t >= o) ? sm[t - o] : 0;
        __syncthreads();
        sm[t] += add;
        __syncthreads();
    }
    if (t < nb) g_bsum[t] = sm[t] - v;
}
__global__ void k_scan3() {
    int i = blockIdx.x * blockDim.x + threadIdx.x;
    if (i < NN) {
        g_rowptr[i + 1] = g_tscan[i] + g_bsum[i >> 10];
        if (i == 0) g_rowptr[0] = 0;
        int d = g_cnt[i];
        g_invdeg[i] = 1.0f / (float)(d > 0 ? d : 1);
        g_cnt[i] = 0;
    }
}
__global__ void k_fill(const int* __restrict__ src, const int* __restrict__ dst) {
    int e = blockIdx.x * blockDim.x + threadIdx.x;
    if (e < NE) {
        int d = dst[e];
        int p = g_rowptr[d] + atomicAdd(&g_cnt[d], 1);
        g_esrc[p] = src[e];
    }
}

// ---------------- prep: weights -> [n][k] K-major bf16 hi/lo (zero-padded) ----------------
__global__ void k_prepW(const float* __restrict__ Wn, const float* __restrict__ Ws,
                        int C, int NT, __nv_bfloat16* __restrict__ oh,
                        __nv_bfloat16* __restrict__ ol) {
    int idx = blockIdx.x * blockDim.x + threadIdx.x;
    if (idx >= NT * 128) return;
    int n = idx >> 7, k = idx & 127;
    float f = 0.f;
    if (n < C) f = Wn[k * C + n];
    else if (n < 2 * C) f = Ws[k * C + (n - C)];
    __nv_bfloat16 h = __float2bfloat16(f);
    oh[idx] = h;
    ol[idx] = __float2bfloat16(f - __bfloat162float(h));
}

// features -> bf16 hi/lo
__global__ void k_splitX(const float4* __restrict__ x4, uint2* __restrict__ xh2,
                         uint2* __restrict__ xl2) {
    int idx = blockIdx.x * blockDim.x + threadIdx.x;
    if (idx >= NN * 32) return;
    float4 v = x4[idx];
    __nv_bfloat16 hx = __float2bfloat16(v.x), hy = __float2bfloat16(v.y);
    __nv_bfloat16 hz = __float2bfloat16(v.z), hw = __float2bfloat16(v.w);
    __nv_bfloat162 h01(hx, hy), h23(hz, hw);
    __nv_bfloat162 l01(__float2bfloat16(v.x - __bfloat162float(hx)),
                       __float2bfloat16(v.y - __bfloat162float(hy)));
    __nv_bfloat162 l23(__float2bfloat16(v.z - __bfloat162float(hz)),
                       __float2bfloat16(v.w - __bfloat162float(hw)));
    xh2[idx] = make_uint2(*(uint32_t*)&h01, *(uint32_t*)&h23);
    xl2[idx] = make_uint2(*(uint32_t*)&l01, *(uint32_t*)&l23);
}

// ---------------- mma.sync bf16 dual GEMM, occ-2, ldmatrix fragments ----------------
__device__ __forceinline__ void mma_bf16(float (&c)[4], const uint32_t (&a)[4],
                                         const uint32_t b0, const uint32_t b1) {
    asm volatile(
        "mma.sync.aligned.m16n8k16.row.col.f32.bf16.bf16.f32 "
        "{%0,%1,%2,%3}, {%4,%5,%6,%7}, {%8,%9}, {%0,%1,%2,%3};\n"
        : "+f"(c[0]), "+f"(c[1]), "+f"(c[2]), "+f"(c[3])
        : "r"(a[0]), "r"(a[1]), "r"(a[2]), "r"(a[3]), "r"(b0), "r"(b1));
}
__device__ __forceinline__ void ldsm_x4(uint32_t (&r)[4], uint32_t addr) {
    asm volatile("ldmatrix.sync.aligned.m8n8.x4.shared.b16 {%0,%1,%2,%3}, [%4];"
                 : "=r"(r[0]), "=r"(r[1]), "=r"(r[2]), "=r"(r[3]) : "r"(addr));
}

// CTA tile: 128 rows x 64 cols of [y | s] concat (width 2C padded).
// y written as fp16, s as fp32 (+bias).
__global__ __launch_bounds__(256, 2) void k_gemm_mma(
    const __nv_bfloat16* __restrict__ xh, const __nv_bfloat16* __restrict__ xl,
    const __nv_bfloat16* __restrict__ wh, const __nv_bfloat16* __restrict__ wl,
    const float* __restrict__ bias, int C,
    __half* __restrict__ y, float* __restrict__ s) {
    extern __shared__ __nv_bfloat16 smarr[];
    __nv_bfloat16* Ah = smarr;                // [128][KP]
    __nv_bfloat16* Al = Ah + 128 * KP;
    __nv_bfloat16* Bh = Al + 128 * KP;        // [64][KP]
    __nv_bfloat16* Bl = Bh + 64 * KP;

    int tid = threadIdx.x;
    int row0 = blockIdx.x * 128;
    int col0 = blockIdx.y * 64;

    for (int idx = tid; idx < 128 * 16; idx += 256) {
        int r = idx >> 4, k = (idx & 15) << 3;
        int grow = row0 + r;
        uint4 vh = make_uint4(0, 0, 0, 0), vl = vh;
        if (grow < NN) {
            vh = *(const uint4*)(xh + grow * 128 + k);
            vl = *(const uint4*)(xl + grow * 128 + k);
        }
        *(uint4*)(Ah + r * KP + k) = vh;
        *(uint4*)(Al + r * KP + k) = vl;
    }
    for (int idx = tid; idx < 64 * 16; idx += 256) {
        int n = idx >> 4, k = (idx & 15) << 3;
        *(uint4*)(Bh + n * KP + k) = *(const uint4*)(wh + (col0 + n) * 128 + k);
        *(uint4*)(Bl + n * KP + k) = *(const uint4*)(wl + (col0 + n) * 128 + k);
    }
    __syncthreads();

    int wid = tid >> 5, lane = tid & 31;
    int mbase = (wid >> 1) * 32;
    int nbase = (wid & 1) * 32;
    int r4 = lane >> 2, tg = lane & 3;

    uint32_t aBase = smem_u32(Ah);
    uint32_t alBase = smem_u32(Al);
    uint32_t bBase = smem_u32(Bh);
    uint32_t blBase = smem_u32(Bl);

    int aRow = mbase + (lane & 15);
    int aOff = aRow * KP + ((lane >> 4) << 3);
    int q = lane >> 3;
    int bRow = nbase + ((q >> 1) << 3) + (lane & 7);
    int bOff = bRow * KP + ((q & 1) << 3);

    float acc[2][4][4];
#pragma unroll
    for (int mi = 0; mi < 2; mi++)
#pragma unroll
        for (int ni = 0; ni < 4; ni++)
#pragma unroll
            for (int c = 0; c < 4; c++) acc[mi][ni][c] = 0.f;

#pragma unroll
    for (int kc = 0; kc < 8; kc++) {
        int k0 = kc * 16;
        uint32_t ah[2][4], al[2][4];
        ldsm_x4(ah[0], aBase + (aOff + k0) * 2);
        ldsm_x4(ah[1], aBase + (aOff + 16 * KP + k0) * 2);
        ldsm_x4(al[0], alBase + (aOff + k0) * 2);
        ldsm_x4(al[1], alBase + (aOff + 16 * KP + k0) * 2);
        uint32_t bh01[4], bh23[4], bl01[4], bl23[4];
        ldsm_x4(bh01, bBase + (bOff + k0) * 2);
        ldsm_x4(bh23, bBase + (bOff + 16 * KP + k0) * 2);
        ldsm_x4(bl01, blBase + (bOff + k0) * 2);
        ldsm_x4(bl23, blBase + (bOff + 16 * KP + k0) * 2);
#pragma unroll
        for (int mi = 0; mi < 2; mi++) {
            mma_bf16(acc[mi][0], ah[mi], bh01[0], bh01[1]);
            mma_bf16(acc[mi][1], ah[mi], bh01[2], bh01[3]);
            mma_bf16(acc[mi][2], ah[mi], bh23[0], bh23[1]);
            mma_bf16(acc[mi][3], ah[mi], bh23[2], bh23[3]);
            mma_bf16(acc[mi][0], al[mi], bh01[0], bh01[1]);
            mma_bf16(acc[mi][1], al[mi], bh01[2], bh01[3]);
            mma_bf16(acc[mi][2], al[mi], bh23[0], bh23[1]);
            mma_bf16(acc[mi][3], al[mi], bh23[2], bh23[3]);
            mma_bf16(acc[mi][0], ah[mi], bl01[0], bl01[1]);
            mma_bf16(acc[mi][1], ah[mi], bl01[2], bl01[3]);
            mma_bf16(acc[mi][2], ah[mi], bl23[0], bl23[1]);
            mma_bf16(acc[mi][3], ah[mi], bl23[2], bl23[3]);
        }
    }

    // epilogue: y -> fp16, s -> fp32 + bias
#pragma unroll
    for (int mi = 0; mi < 2; mi++) {
#pragma unroll
        for (int ni = 0; ni < 4; ni++) {
            int grow0 = row0 + mbase + mi * 16 + r4;
            int cc = col0 + nbase + ni * 8 + tg * 2;
            if (cc >= 2 * C) continue;
#pragma unroll
            for (int half = 0; half < 2; half++) {
                int grow = grow0 + half * 8;
                if (grow >= NN) continue;
                float v0 = acc[mi][ni][half * 2 + 0];
                float v1 = acc[mi][ni][half * 2 + 1];
                if (cc < C) {
                    __half2 hv = __floats2half2_rn(v0, v1);
                    *(uint32_t*)(y + grow * C + cc) = *(uint32_t*)&hv;
                } else {
                    int c = cc - C;
                    *(float2*)(s + grow * C + c) =
                        make_float2(v0 + bias[c], v1 + bias[c + 1]);
                }
            }
        }
    }
}

// ---------------- warp-per-node gather (fp16 y) + finalize (F=128) -> bf16 hi/lo ----------------
__global__ void k_aggfin128sp(const uint2* __restrict__ y2, const float4* __restrict__ s4,
                              uint2* __restrict__ xh2, uint2* __restrict__ xl2) {
    int n = (blockIdx.x * blockDim.x + threadIdx.x) >> 5;
    int lane = threadIdx.x & 31;
    if (n >= NN) return;
    int r0 = g_rowptr[n], r1 = g_rowptr[n + 1];
    float4 acc = make_float4(0.f, 0.f, 0.f, 0.f);
    for (int base = r0; base < r1; base += 32) {
        int idx = base + lane;
        int sid = (idx < r1) ? g_esrc[idx] : 0;
        int m = r1 - base;
        if (m > 32) m = 32;
#pragma unroll 4
        for (int j = 0; j < m; j++) {
            int sn = __shfl_sync(0xffffffffu, sid, j);
            uint2 v = y2[sn * 32 + lane];   // 4 halves
            float2 p0 = __half22float2(*(__half2*)&v.x);
            float2 p1 = __half22float2(*(__half2*)&v.y);
            acc.x += p0.x; acc.y += p0.y; acc.z += p1.x; acc.w += p1.y;
        }
    }
    float id = g_invdeg[n];
    float4 sv = s4[n * 32 + lane];
    float4 o;
    o.x = fmaxf(sv.x + acc.x * id, 0.f);
    o.y = fmaxf(sv.y + acc.y * id, 0.f);
    o.z = fmaxf(sv.z + acc.z * id, 0.f);
    o.w = fmaxf(sv.w + acc.w * id, 0.f);
    __nv_bfloat16 hx = __float2bfloat16(o.x), hy = __float2bfloat16(o.y);
    __nv_bfloat16 hz = __float2bfloat16(o.z), hw = __float2bfloat16(o.w);
    __nv_bfloat162 h01(hx, hy), h23(hz, hw);
    __nv_bfloat162 l01(__float2bfloat16(o.x - __bfloat162float(hx)),
                       __float2bfloat16(o.y - __bfloat162float(hy)));
    __nv_bfloat162 l23(__float2bfloat16(o.z - __bfloat162float(hz)),
                       __float2bfloat16(o.w - __bfloat162float(hw)));
    xh2[n * 32 + lane] = make_uint2(*(uint32_t*)&h01, *(uint32_t*)&h23);
    xl2[n * 32 + lane] = make_uint2(*(uint32_t*)&l01, *(uint32_t*)&l23);
}

// ---------------- warp-per-node gather (fp16 y) + finalize (F=40) ----------------
__global__ void k_aggfin40(const uint32_t* __restrict__ y32, const float* __restrict__ s,
                           float* __restrict__ out) {
    int n = (blockIdx.x * blockDim.x + threadIdx.x) >> 5;
    int lane = threadIdx.x & 31;
    if (n >= NN) return;
    int r0 = g_rowptr[n], r1 = g_rowptr[n + 1];
    float2 acc = make_float2(0.f, 0.f);
    for (int base = r0; base < r1; base += 32) {
        int idx = base + lane;
        int sid = (idx < r1) ? g_esrc[idx] : 0;
        int m = r1 - base;
        if (m > 32) m = 32;
#pragma unroll 4
        for (int j = 0; j < m; j++) {
            int sn = __shfl_sync(0xffffffffu, sid, j);
            if (lane < 20) {
                uint32_t v = y32[sn * 20 + lane];   // 2 halves
                float2 p = __half22float2(*(__half2*)&v);
                acc.x += p.x; acc.y += p.y;
            }
        }
    }
    if (lane < 20) {
        float id = g_invdeg[n];
        const float* sr = s + n * 40 + lane * 2;
        float2 o = make_float2(sr[0] + acc.x * id, sr[1] + acc.y * id);
        *(float2*)(out + n * 40 + lane * 2) = o;
    }
}

// ---------------- launch ----------------
extern "C" void kernel_launch(void* const* d_in, const int* in_sizes, int n_in,
                              void* d_out, int out_size) {
    const float* feat = (const float*)d_in[0];
    const int* src = (const int*)d_in[1];
    const int* dst = (const int*)d_in[2];
    const float* Ws1 = (const float*)d_in[3];
    const float* Wn1 = (const float*)d_in[4];
    const float* b1  = (const float*)d_in[5];
    const float* Ws2 = (const float*)d_in[6];
    const float* Wn2 = (const float*)d_in[7];
    const float* b2  = (const float*)d_in[8];
    const float* Ws3 = (const float*)d_in[9];
    const float* Wn3 = (const float*)d_in[10];
    const float* b3  = (const float*)d_in[11];
    float* out = (float*)d_out;

    __half* py;
    float* ps;
    __nv_bfloat16 *pxh, *pxl, *pw1h, *pw1l, *pw2h, *pw2l, *pw3h, *pw3l;
    cudaGetSymbolAddress((void**)&py, g_y);
    cudaGetSymbolAddress((void**)&ps, g_s);
    cudaGetSymbolAddress((void**)&pxh, g_xh);
    cudaGetSymbolAddress((void**)&pxl, g_xl);
    cudaGetSymbolAddress((void**)&pw1h, g_w1h);
    cudaGetSymbolAddress((void**)&pw1l, g_w1l);
    cudaGetSymbolAddress((void**)&pw2h, g_w2h);
    cudaGetSymbolAddress((void**)&pw2l, g_w2l);
    cudaGetSymbolAddress((void**)&pw3h, g_w3h);
    cudaGetSymbolAddress((void**)&pw3l, g_w3l);

    const int SMEM = (128 + 128 + 64 + 64) * KP * 2;  // 104448
    cudaFuncSetAttribute(k_gemm_mma, cudaFuncAttributeMaxDynamicSharedMemorySize, SMEM);

    int nbN = (NN + 255) / 256;
    int nbE = (NE + 255) / 256;
    int nbScan = (NN + 1023) / 1024;
    int gRows = (NN + 127) / 128;   // 782
    int gAgg = (NN + 7) / 8;

    // prep (independent of CSR)
    k_prepW<<<(256 * 128 + 255) / 256, 256>>>(Wn1, Ws1, 128, 256, pw1h, pw1l);
    k_prepW<<<(256 * 128 + 255) / 256, 256>>>(Wn2, Ws2, 128, 256, pw2h, pw2l);
    k_prepW<<<(128 * 128 + 255) / 256, 256>>>(Wn3, Ws3, 40, 128, pw3h, pw3l);
    k_splitX<<<(NN * 32 + 255) / 256, 256>>>((const float4*)feat, (uint2*)pxh, (uint2*)pxl);

    // CSR build
    k_zero_cnt<<<nbN, 256>>>();
    k_count<<<nbE, 256>>>(dst);
    k_scan1<<<nbScan, 1024>>>();
    k_scan2<<<1, 128>>>(nbScan);
    k_scan3<<<nbN, 256>>>();
    k_fill<<<nbE, 256>>>(src, dst);

    // layer 1
    k_gemm_mma<<<dim3(gRows, 4), 256, SMEM>>>(pxh, pxl, pw1h, pw1l, b1, 128, py, ps);
    k_aggfin128sp<<<gAgg, 256>>>((const uint2*)py, (const float4*)ps, (uint2*)pxh, (uint2*)pxl);
    // layer 2
    k_gemm_mma<<<dim3(gRows, 4), 256, SMEM>>>(pxh, pxl, pw2h, pw2l, b2, 128, py, ps);
    k_aggfin128sp<<<gAgg, 256>>>((const uint2*)py, (const float4*)ps, (uint2*)pxh, (uint2*)pxl);
    // layer 3 (N padded to 128: cols 0..39 -> y fp16, 40..79 -> s)
    k_gemm_mma<<<dim3(gRows, 2), 256, SMEM>>>(pxh, pxl, pw3h, pw3l, b3, 40, py, ps);
    k_aggfin40<<<gAgg, 256>>>((const uint32_t*)py, ps, out);
}